// round 5
// baseline (speedup 1.0000x reference)
#include <cuda_runtime.h>
#include <cstdint>
#include <math.h>

// Problem constants (fixed shapes for this problem)
#define NTOK 8192          // B*T
#define HDIM 1024
#define IDIM 2048
#define NEXP 8
#define NSLOT (NTOK*2)     // top_k = 2

// ---------------- scratch (device globals: no allocations allowed) ----------
__device__ int   g_counts[NEXP];
__device__ int   g_cursors[NEXP];
__device__ int   g_offsets[NEXP+1];
__device__ int   g_topk_idx[NTOK*2];
__device__ float g_topk_val[NTOK*2];
__device__ int   g_slot_tok[NSLOT];
__device__ float g_slot_w[NSLOT];
__device__ float g_hid[(size_t)NSLOT * IDIM];   // 128 MB fc1 activations

// ---------------- helpers ----------------------------------------------------
__device__ __forceinline__ float to_tf32(float x){
  uint32_t u; asm("cvt.rna.tf32.f32 %0, %1;" : "=r"(u) : "f"(x));
  return __uint_as_float(u);
}
__device__ __forceinline__ float silu_f(float v){
  return v * (1.0f / (1.0f + __expf(-v)));
}
__device__ __forceinline__ void sts4_tf32(float* p, float4 v){
  p[0] = to_tf32(v.x); p[1] = to_tf32(v.y); p[2] = to_tf32(v.z); p[3] = to_tf32(v.w);
}
__device__ __forceinline__ void mma_tf32(float* c, const uint32_t* a, const uint32_t* b){
  asm volatile(
    "mma.sync.aligned.m16n8k8.row.col.f32.tf32.tf32.f32 "
    "{%0,%1,%2,%3}, {%4,%5,%6,%7}, {%8,%9}, {%0,%1,%2,%3};\n"
    : "+f"(c[0]), "+f"(c[1]), "+f"(c[2]), "+f"(c[3])
    : "r"(a[0]), "r"(a[1]), "r"(a[2]), "r"(a[3]),
      "r"(b[0]), "r"(b[1]));
}

// ---------------- routing kernels --------------------------------------------
__global__ void k_init(){
  if (threadIdx.x < NEXP) g_counts[threadIdx.x] = 0;
}

// One warp per token: logits = x . Wg^T (fp32 exact), softmax, top-2.
__global__ void k_gate(const float* __restrict__ x, const float* __restrict__ Wg){
  int gid  = blockIdx.x * blockDim.x + threadIdx.x;
  int n    = gid >> 5;
  int lane = gid & 31;
  if (n >= NTOK) return;
  const float* xr = x + (size_t)n * HDIM;
  float acc[NEXP];
  #pragma unroll
  for (int e = 0; e < NEXP; ++e) acc[e] = 0.f;
  for (int h = lane; h < HDIM; h += 32){
    float xv = xr[h];
    #pragma unroll
    for (int e = 0; e < NEXP; ++e) acc[e] = fmaf(xv, Wg[e*HDIM + h], acc[e]);
  }
  #pragma unroll
  for (int e = 0; e < NEXP; ++e){
    #pragma unroll
    for (int o = 16; o > 0; o >>= 1) acc[e] += __shfl_xor_sync(0xffffffffu, acc[e], o);
  }
  // softmax (all lanes compute identically)
  float mx = acc[0];
  #pragma unroll
  for (int e = 1; e < NEXP; ++e) mx = fmaxf(mx, acc[e]);
  float p[NEXP], s = 0.f;
  #pragma unroll
  for (int e = 0; e < NEXP; ++e){ p[e] = __expf(acc[e] - mx); s += p[e]; }
  float inv = 1.f / s;
  // top-2, strict > keeps lowest index on ties (matches jax.lax.top_k)
  int i0 = 0; float v0 = p[0];
  #pragma unroll
  for (int e = 1; e < NEXP; ++e) if (p[e] > v0){ v0 = p[e]; i0 = e; }
  int i1 = -1; float v1 = -1.f;
  #pragma unroll
  for (int e = 0; e < NEXP; ++e) if (e != i0 && p[e] > v1){ v1 = p[e]; i1 = e; }
  if (lane == 0){
    g_topk_idx[2*n]   = i0; g_topk_val[2*n]   = v0 * inv;
    g_topk_idx[2*n+1] = i1; g_topk_val[2*n+1] = v1 * inv;
    atomicAdd(&g_counts[i0], 1);
    atomicAdd(&g_counts[i1], 1);
  }
}

__global__ void k_offsets(){
  if (threadIdx.x == 0){
    int s = 0;
    for (int e = 0; e < NEXP; ++e){ g_offsets[e] = s; g_cursors[e] = s; s += g_counts[e]; }
    g_offsets[NEXP] = s;
  }
}

__global__ void k_scatter(){
  int n = blockIdx.x * blockDim.x + threadIdx.x;
  if (n >= NTOK) return;
  #pragma unroll
  for (int k = 0; k < 2; ++k){
    int e   = g_topk_idx[2*n + k];
    int pos = atomicAdd(&g_cursors[e], 1);
    g_slot_tok[pos] = n;
    g_slot_w[pos]   = g_topk_val[2*n + k];
  }
}

// ---------------- grouped GEMM ------------------------------------------------
// MODE 0 (fc1): C[slot, i] = silu( sum_h x[tok[slot],h] * W1[e,i,h] ) -> g_hid
//   A: gathered x rows (K = HDIM), B: W1[e] rows i (k-contig), N = IDIM
// MODE 1 (fc2): out[tok, h] += w_slot * sum_i g_hid[slot,i] * W2[e,h,i]
//   A: g_hid rows (K = IDIM), B: W2[e] rows h (k-contig), N = HDIM
// Tile: BM=BN=64, BK=16, 128 threads (4 warps, 2x2), warp tile 32x32,
// mma.sync.m16n8k8 tf32, register-staged double buffer of smem tiles.
template<int MODE>
__global__ __launch_bounds__(128) void k_gemm(const float* __restrict__ Asrc,
                                              const float* __restrict__ Wsrc,
                                              float* __restrict__ Out){
  constexpr int KD = (MODE == 0) ? HDIM : IDIM;
  constexpr int KT = KD / 16;

  const int e   = blockIdx.z;
  const int off = g_offsets[e];
  const int Me  = g_offsets[e+1] - off;
  const int m0  = blockIdx.y * 64;
  if (m0 >= Me) return;
  const int n0  = blockIdx.x * 64;
  const float* Bbase = Wsrc + (size_t)e * (size_t)HDIM * (size_t)IDIM;

  __shared__ float As[64][20];
  __shared__ float Bs[64][20];
  __shared__ const float* Arow[64];
  __shared__ int   rowTok[64];
  __shared__ float rowW[64];

  const int tid = threadIdx.x;
  if (tid < 64){
    int gr = m0 + tid;
    if (gr < Me){
      int slot = off + gr;
      if (MODE == 0){
        Arow[tid]   = Asrc + (size_t)g_slot_tok[slot] * HDIM;
        rowTok[tid] = slot;                 // hid row to write
        rowW[tid]   = 0.f;
      } else {
        Arow[tid]   = g_hid + (size_t)slot * IDIM;
        rowTok[tid] = g_slot_tok[slot];     // output token row
        rowW[tid]   = g_slot_w[slot];
      }
    } else {
      Arow[tid]   = (MODE == 0) ? Asrc : g_hid;  // safe dummy row
      rowTok[tid] = -1;
      rowW[tid]   = 0.f;
    }
  }
  __syncthreads();

  // per-thread load pointers: 2 rows of A and 2 rows of B, one float4 each
  const int lr = tid >> 2;          // 0..31
  const int lc = (tid & 3) * 4;     // 0,4,8,12
  const float* apt0 = Arow[lr]      + lc;
  const float* apt1 = Arow[lr + 32] + lc;
  const float* bpt0 = Bbase + (size_t)(n0 + lr)      * KD + lc;
  const float* bpt1 = Bbase + (size_t)(n0 + lr + 32) * KD + lc;
  float* as0 = &As[lr][lc];
  float* as1 = &As[lr + 32][lc];
  float* bs0 = &Bs[lr][lc];
  float* bs1 = &Bs[lr + 32][lc];

  const int lane = tid & 31, warp = tid >> 5;
  const int wm = warp >> 1, wn = warp & 1;
  const int g = lane >> 2, tig = lane & 3;

  float c[2][4][4];
  #pragma unroll
  for (int mi = 0; mi < 2; ++mi)
    #pragma unroll
    for (int ni = 0; ni < 4; ++ni)
      #pragma unroll
      for (int j = 0; j < 4; ++j) c[mi][ni][j] = 0.f;

  // prologue: stage tile 0
  float4 fa0 = *(const float4*)apt0;
  float4 fa1 = *(const float4*)apt1;
  float4 fb0 = *(const float4*)bpt0;
  float4 fb1 = *(const float4*)bpt1;
  sts4_tf32(as0, fa0); sts4_tf32(as1, fa1);
  sts4_tf32(bs0, fb0); sts4_tf32(bs1, fb1);
  __syncthreads();

  for (int kt = 0; kt < KT; ++kt){
    const bool more = (kt + 1 < KT);
    if (more){
      const int ko = (kt + 1) * 16;
      fa0 = *(const float4*)(apt0 + ko);
      fa1 = *(const float4*)(apt1 + ko);
      fb0 = *(const float4*)(bpt0 + ko);
      fb1 = *(const float4*)(bpt1 + ko);
    }
    #pragma unroll
    for (int ks = 0; ks < 2; ++ks){
      const int k0 = ks * 8;
      uint32_t a[2][4], b[4][2];
      #pragma unroll
      for (int mi = 0; mi < 2; ++mi){
        int r = wm*32 + mi*16 + g;
        a[mi][0] = __float_as_uint(As[r    ][k0 + tig]);
        a[mi][1] = __float_as_uint(As[r + 8][k0 + tig]);
        a[mi][2] = __float_as_uint(As[r    ][k0 + tig + 4]);
        a[mi][3] = __float_as_uint(As[r + 8][k0 + tig + 4]);
      }
      #pragma unroll
      for (int ni = 0; ni < 4; ++ni){
        int bn = wn*32 + ni*8 + g;
        b[ni][0] = __float_as_uint(Bs[bn][k0 + tig]);
        b[ni][1] = __float_as_uint(Bs[bn][k0 + tig + 4]);
      }
      #pragma unroll
      for (int mi = 0; mi < 2; ++mi)
        #pragma unroll
        for (int ni = 0; ni < 4; ++ni)
          mma_tf32(c[mi][ni], a[mi], b[ni]);
    }
    __syncthreads();
    if (more){
      sts4_tf32(as0, fa0); sts4_tf32(as1, fa1);
      sts4_tf32(bs0, fb0); sts4_tf32(bs1, fb1);
    }
    __syncthreads();
  }

  // epilogue
  #pragma unroll
  for (int mi = 0; mi < 2; ++mi){
    const int r0 = wm*32 + mi*16 + g;
    const int r1 = r0 + 8;
    const int t0 = rowTok[r0];
    const int t1 = rowTok[r1];
    if (MODE == 0){
      #pragma unroll
      for (int ni = 0; ni < 4; ++ni){
        const int col = n0 + wn*32 + ni*8 + 2*tig;
        if (t0 >= 0){
          float2 v = make_float2(silu_f(c[mi][ni][0]), silu_f(c[mi][ni][1]));
          *(float2*)(g_hid + (size_t)t0 * IDIM + col) = v;
        }
        if (t1 >= 0){
          float2 v = make_float2(silu_f(c[mi][ni][2]), silu_f(c[mi][ni][3]));
          *(float2*)(g_hid + (size_t)t1 * IDIM + col) = v;
        }
      }
    } else {
      const float w0 = rowW[r0];
      const float w1 = rowW[r1];
      #pragma unroll
      for (int ni = 0; ni < 4; ++ni){
        const int col = n0 + wn*32 + ni*8 + 2*tig;
        if (t0 >= 0){
          atomicAdd(Out + (size_t)t0 * HDIM + col,     w0 * c[mi][ni][0]);
          atomicAdd(Out + (size_t)t0 * HDIM + col + 1, w0 * c[mi][ni][1]);
        }
        if (t1 >= 0){
          atomicAdd(Out + (size_t)t1 * HDIM + col,     w1 * c[mi][ni][2]);
          atomicAdd(Out + (size_t)t1 * HDIM + col + 1, w1 * c[mi][ni][3]);
        }
      }
    }
  }
}

// ---------------- launch ------------------------------------------------------
extern "C" void kernel_launch(void* const* d_in, const int* in_sizes, int n_in,
                              void* d_out, int out_size){
  const float* x  = (const float*)d_in[0];   // [4,2048,1024]
  const float* Wg = (const float*)d_in[1];   // [8,1024]
  const float* W1 = (const float*)d_in[2];   // [8,2048,1024]
  const float* W2 = (const float*)d_in[3];   // [8,1024,2048]
  float* out = (float*)d_out;                // [4,2048,1024]
  (void)in_sizes; (void)n_in; (void)out_size; // top_k hardcoded = 2

  cudaMemsetAsync(out, 0, (size_t)NTOK * HDIM * sizeof(float));
  k_init<<<1, 32>>>();
  k_gate<<<NTOK/8, 256>>>(x, Wg);
  k_offsets<<<1, 32>>>();
  k_scatter<<<NTOK/256, 256>>>();
  // fc1: N = IDIM (2048) -> 32 n-tiles; up to 128 m-tiles per expert (early exit)
  k_gemm<0><<<dim3(IDIM/64, NTOK/64, NEXP), 128>>>(x, W1, nullptr);
  // fc2: N = HDIM (1024) -> 16 n-tiles
  k_gemm<1><<<dim3(HDIM/64, NTOK/64, NEXP), 128>>>(nullptr, W2, out);
}